// round 5
// baseline (speedup 1.0000x reference)
#include <cuda_runtime.h>
#include <cuda_bf16.h>
#include <math.h>

#define B_   8
#define L_   1024
#define H_   8
#define D_   32
#define C_   256
#define QT   128     // query tile
#define KT   64      // key tile
#define NKT  (L_ / KT)
#define SCALE 0.17677669529663687f  // 1/sqrt(32)

// smem layout (floats)
#define QTR_OFF  0                      // Qtr[32][128] swizzled, 4096
#define KTR_OFF  (QTR_OFF + 32*128)     // Ktr[32][64]  swizzled, 2048
#define VS_OFF   (KTR_OFF + 32*64)      // Vs[64][36], 2304
#define SS_OFF   (VS_OFF  + 64*36)      // Ss[128][68], 8704
#define MADD_OFF (SS_OFF  + 128*68)     // Madd[64]
#define SMEM_FLOATS (MADD_OFF + 64)
#define SMEM_BYTES  (SMEM_FLOATS * 4)   // 68864 B

// mask dtype mode: 0 = float32, 1 = int32, 2 = uint8
__device__ int g_mask_mode;

__global__ void detect_mask_mode(const unsigned int* m)
{
    bool all_f32 = true, all_i32 = true;
    for (int i = 0; i < 2048; ++i) {
        unsigned int w = m[i];
        if (w != 0u && w != 0x3f800000u) all_f32 = false;
        if (w != 0u && w != 1u)          all_i32 = false;
    }
    g_mask_mode = all_f32 ? 0 : (all_i32 ? 1 : 2);
}

__device__ __forceinline__ bool mask_at(const void* m, int idx, int mode)
{
    if (mode == 0) return ((const float*)m)[idx] != 0.0f;
    if (mode == 1) return ((const int*)m)[idx]   != 0;
    return ((const unsigned char*)m)[idx] != 0;
}

// ---- f32x2 packed helpers (sm_10x) ----
typedef unsigned long long ull;

__device__ __forceinline__ ull pack2(float x, float y) {
    ull r; asm("mov.b64 %0, {%1,%2};" : "=l"(r) : "f"(x), "f"(y)); return r;
}
__device__ __forceinline__ void unpack2(ull a, float& x, float& y) {
    asm("mov.b64 {%0,%1}, %2;" : "=f"(x), "=f"(y) : "l"(a));
}
__device__ __forceinline__ ull ffma2(ull a, ull b, ull c) {
    ull r; asm("fma.rn.f32x2 %0, %1, %2, %3;" : "=l"(r) : "l"(a), "l"(b), "l"(c)); return r;
}
__device__ __forceinline__ ull fmul2(ull a, ull b) {
    ull r; asm("mul.rn.f32x2 %0, %1, %2;" : "=l"(r) : "l"(a), "l"(b)); return r;
}

__global__ __launch_bounds__(256, 2)
void masked_attn_kernel(const float* __restrict__ q,
                        const float* __restrict__ k,
                        const float* __restrict__ v,
                        const void* __restrict__ mask,
                        const float* __restrict__ bias,
                        float* __restrict__ out)
{
    extern __shared__ float sm[];
    float* Qtr  = sm + QTR_OFF;
    float* Ktr  = sm + KTR_OFF;
    float* Vs   = sm + VS_OFF;
    float* Ss   = sm + SS_OFF;
    float* Madd = sm + MADD_OFF;

    // block -> (b, h, q-tile)
    int blk = blockIdx.x;
    int qt  = blk & 7;            // 8 q-tiles of 128
    int h   = (blk >> 3) & 7;
    int b   = blk >> 6;
    int q0  = qt * QT;

    int mode = g_mask_mode;
    int t  = threadIdx.x;
    int tx = t & 15, ty = t >> 4;  // Phase A: cols tx*4..+3, rows ty*8..+7
    int rp = t >> 2, qd = t & 3;   // Phase B: rows 2rp..2rp+1, channels qd*8..+7

    // ---- load Q tile transposed+swizzled: Qtr[d][r] ----
    {
        const float* qbase = q + ((size_t)(b * L_ + q0)) * C_ + h * D_;
        #pragma unroll
        for (int it = 0; it < 16; ++it) {
            int i  = t + it * 256;
            int rr = i >> 5, dd = i & 31;
            float qv = qbase[(size_t)rr * C_ + dd];
            int addr = dd * 128 + ((((rr >> 2) ^ (dd & 15)) << 2) | (rr & 3));
            Qtr[addr] = qv;
        }
    }

    float m0 = -INFINITY, m1 = -INFINITY, l0 = 0.f, l1 = 0.f;
    ull acc[8];   // acc[0..3] row0 ch qd*8..+7, acc[4..7] row1
    #pragma unroll
    for (int c = 0; c < 8; ++c) acc[c] = 0ull;

    for (int kt = 0; kt < NKT; ++kt) {
        int k0 = kt * KT;
        __syncthreads();   // prev iteration's reads of Ktr/Vs done

        // ---- load K (transposed+swizzled) and V tiles ----
        const float* kbase = k + ((size_t)(b * L_ + k0)) * C_ + h * D_;
        const float* vbase = v + ((size_t)(b * L_ + k0)) * C_ + h * D_;
        #pragma unroll
        for (int it = 0; it < 8; ++it) {
            int i  = t + it * 256;
            int rr = i >> 5, dd = i & 31;
            float kv = kbase[(size_t)rr * C_ + dd];
            float vv = vbase[(size_t)rr * C_ + dd];
            int kaddr = dd * 64 + ((((rr >> 2) ^ (dd & 15)) << 2) | (rr & 3));
            Ktr[kaddr]       = kv;
            Vs[rr * 36 + dd] = vv;
        }
        if (t < KT)
            Madd[t] = mask_at(mask, b * L_ + k0 + t, mode) ? 0.f : -1e9f;
        __syncthreads();

        // ---- Phase A: scores 128x64, 8x4 micro-tile, packed f32x2 ----
        ull a2[4][4];   // [row-pair][col]
        #pragma unroll
        for (int rpp = 0; rpp < 4; ++rpp)
            #pragma unroll
            for (int i = 0; i < 4; ++i) a2[rpp][i] = 0ull;

        #pragma unroll 8
        for (int d = 0; d < D_; ++d) {
            int sw = d & 15;
            float4 kf = *(const float4*)&Ktr[d * 64 + ((tx ^ sw) << 2)];
            ull kk[4];
            kk[0] = pack2(kf.x, kf.x);
            kk[1] = pack2(kf.y, kf.y);
            kk[2] = pack2(kf.z, kf.z);
            kk[3] = pack2(kf.w, kf.w);
            ulonglong2 qa = *(const ulonglong2*)&Qtr[d * 128 + (((2 * ty)     ^ sw) << 2)];
            ulonglong2 qb = *(const ulonglong2*)&Qtr[d * 128 + (((2 * ty + 1) ^ sw) << 2)];
            ull q2[4] = { qa.x, qa.y, qb.x, qb.y };
            #pragma unroll
            for (int rpp = 0; rpp < 4; ++rpp)
                #pragma unroll
                for (int i = 0; i < 4; ++i)
                    a2[rpp][i] = ffma2(q2[rpp], kk[i], a2[rpp][i]);
        }

        // scale + bias + mask, write Ss
        {
            float4 madd4 = *(const float4*)&Madd[tx * 4];
            #pragma unroll
            for (int rpp = 0; rpp < 4; ++rpp) {
                float s0[4], s1[4];
                #pragma unroll
                for (int i = 0; i < 4; ++i) unpack2(a2[rpp][i], s0[i], s1[i]);
                #pragma unroll
                for (int e = 0; e < 2; ++e) {
                    int rr = ty * 8 + rpp * 2 + e;
                    const float* sp = e ? s1 : s0;
                    float4 bp = *(const float4*)&bias[((size_t)b * L_ + (q0 + rr)) * L_ + k0 + tx * 4];
                    float4 sv;
                    sv.x = fmaf(sp[0], SCALE, bp.x + madd4.x);
                    sv.y = fmaf(sp[1], SCALE, bp.y + madd4.y);
                    sv.z = fmaf(sp[2], SCALE, bp.z + madd4.z);
                    sv.w = fmaf(sp[3], SCALE, bp.w + madd4.w);
                    *(float4*)&Ss[rr * 68 + tx * 4] = sv;
                }
            }
        }
        __syncwarp();   // Ss rows [16w,16w+16) produced & consumed by warp w only

        // ---- Phase B: online softmax (register-resident) + P*V ----
        float* srow0 = &Ss[(2 * rp) * 68];
        float* srow1 = srow0 + 68;
        int jb = qd * 16;

        // row 0: load 16 scores, rowmax, exp, partial sum, store p
        {
            float4 sv[4];
            #pragma unroll
            for (int g = 0; g < 4; ++g) sv[g] = *(const float4*)&srow0[jb + 4 * g];
            float mt = -INFINITY;
            #pragma unroll
            for (int g = 0; g < 4; ++g)
                mt = fmaxf(mt, fmaxf(fmaxf(sv[g].x, sv[g].y), fmaxf(sv[g].z, sv[g].w)));
            mt = fmaxf(mt, __shfl_xor_sync(0xffffffffu, mt, 1));
            mt = fmaxf(mt, __shfl_xor_sync(0xffffffffu, mt, 2));
            float mnew   = fmaxf(m0, mt);
            float factor = __expf(m0 - mnew);
            l0 *= factor;
            ull f2 = pack2(factor, factor);
            #pragma unroll
            for (int c = 0; c < 4; ++c) acc[c] = fmul2(acc[c], f2);
            #pragma unroll
            for (int g = 0; g < 4; ++g) {
                sv[g].x = __expf(sv[g].x - mnew);
                sv[g].y = __expf(sv[g].y - mnew);
                sv[g].z = __expf(sv[g].z - mnew);
                sv[g].w = __expf(sv[g].w - mnew);
                l0 += sv[g].x + sv[g].y + sv[g].z + sv[g].w;
                *(float4*)&srow0[jb + 4 * g] = sv[g];
            }
            m0 = mnew;
        }
        // row 1
        {
            float4 sv[4];
            #pragma unroll
            for (int g = 0; g < 4; ++g) sv[g] = *(const float4*)&srow1[jb + 4 * g];
            float mt = -INFINITY;
            #pragma unroll
            for (int g = 0; g < 4; ++g)
                mt = fmaxf(mt, fmaxf(fmaxf(sv[g].x, sv[g].y), fmaxf(sv[g].z, sv[g].w)));
            mt = fmaxf(mt, __shfl_xor_sync(0xffffffffu, mt, 1));
            mt = fmaxf(mt, __shfl_xor_sync(0xffffffffu, mt, 2));
            float mnew   = fmaxf(m1, mt);
            float factor = __expf(m1 - mnew);
            l1 *= factor;
            ull f2 = pack2(factor, factor);
            #pragma unroll
            for (int c = 4; c < 8; ++c) acc[c] = fmul2(acc[c], f2);
            #pragma unroll
            for (int g = 0; g < 4; ++g) {
                sv[g].x = __expf(sv[g].x - mnew);
                sv[g].y = __expf(sv[g].y - mnew);
                sv[g].z = __expf(sv[g].z - mnew);
                sv[g].w = __expf(sv[g].w - mnew);
                l1 += sv[g].x + sv[g].y + sv[g].z + sv[g].w;
                *(float4*)&srow1[jb + 4 * g] = sv[g];
            }
            m1 = mnew;
        }
        __syncwarp();   // p values for both rows complete (written by same warp)

        // P*V: both rows share every V load; 8 channels per thread
        const float* vsb = &Vs[qd * 8];
        #pragma unroll 2
        for (int jq = 0; jq < 16; ++jq) {
            float4 p0 = *(const float4*)&srow0[jq * 4];
            float4 p1 = *(const float4*)&srow1[jq * 4];
            #pragma unroll
            for (int u = 0; u < 4; ++u) {
                const float* vrow = vsb + (jq * 4 + u) * 36;
                ulonglong2 va = *(const ulonglong2*)&vrow[0];   // ch qd*8+0..3
                ulonglong2 vb = *(const ulonglong2*)&vrow[4];   // ch qd*8+4..7
                float pu0 = (&p0.x)[u], pu1 = (&p1.x)[u];
                ull pp0 = pack2(pu0, pu0);
                ull pp1 = pack2(pu1, pu1);
                acc[0] = ffma2(pp0, va.x, acc[0]);
                acc[1] = ffma2(pp0, va.y, acc[1]);
                acc[2] = ffma2(pp0, vb.x, acc[2]);
                acc[3] = ffma2(pp0, vb.y, acc[3]);
                acc[4] = ffma2(pp1, va.x, acc[4]);
                acc[5] = ffma2(pp1, va.y, acc[5]);
                acc[6] = ffma2(pp1, vb.x, acc[6]);
                acc[7] = ffma2(pp1, vb.y, acc[7]);
            }
        }
    }

    // ---- epilogue ----
    l0 += __shfl_xor_sync(0xffffffffu, l0, 1);
    l0 += __shfl_xor_sync(0xffffffffu, l0, 2);
    l1 += __shfl_xor_sync(0xffffffffu, l1, 1);
    l1 += __shfl_xor_sync(0xffffffffu, l1, 2);
    float inv0 = 1.f / l0;
    float inv1 = 1.f / l1;

    #pragma unroll
    for (int e = 0; e < 2; ++e) {
        int qrow = q0 + 2 * rp + e;
        float inv = e ? inv1 : inv0;
        const ull* ac = e ? (acc + 4) : acc;
        bool act = mask_at(mask, b * L_ + qrow, mode);
        float* op       = out + ((size_t)(b * L_ + qrow)) * C_ + h * D_ + qd * 8;
        const float* vp = v   + ((size_t)(b * L_ + qrow)) * C_ + h * D_ + qd * 8;
        if (act) {
            #pragma unroll
            for (int g = 0; g < 2; ++g) {
                float x0, x1, x2, x3;
                unpack2(ac[2 * g],     x0, x1);
                unpack2(ac[2 * g + 1], x2, x3);
                ((float4*)op)[g] = make_float4(x0 * inv, x1 * inv, x2 * inv, x3 * inv);
            }
        } else {
            #pragma unroll
            for (int g = 0; g < 2; ++g)
                ((float4*)op)[g] = ((const float4*)vp)[g];
        }
    }
}

extern "C" void kernel_launch(void* const* d_in, const int* in_sizes, int n_in,
                              void* d_out, int out_size)
{
    const int QKV_N  = B_ * L_ * C_;
    const int BIAS_N = B_ * L_ * L_;
    const int MASK_N = B_ * L_;

    int bias_i = -1, mask_i = -1;
    int big[3]; int nbig = 0;
    for (int i = 0; i < n_in; ++i) {
        if (in_sizes[i] == BIAS_N) bias_i = i;
        else if (in_sizes[i] == MASK_N) mask_i = i;
        else if (in_sizes[i] == QKV_N && nbig < 3) big[nbig++] = i;
    }

    const float* q; const float* k; const float* v;
    if (bias_i == 0) {  // alphabetical order: bias, hard_mask, key, query, value
        k = (const float*)d_in[big[0]];
        q = (const float*)d_in[big[1]];
        v = (const float*)d_in[big[2]];
    } else {            // dict order: query, key, value, hard_mask, bias
        q = (const float*)d_in[big[0]];
        k = (const float*)d_in[big[1]];
        v = (const float*)d_in[big[2]];
    }
    const void*  mask = d_in[mask_i];
    const float* bias = (const float*)d_in[bias_i];
    float*       out  = (float*)d_out;

    cudaFuncSetAttribute(masked_attn_kernel,
                         cudaFuncAttributeMaxDynamicSharedMemorySize, SMEM_BYTES);

    detect_mask_mode<<<1, 1>>>((const unsigned int*)mask);

    dim3 grid(B_ * H_ * (L_ / QT));   // 512 blocks
    dim3 block(256);
    masked_attn_kernel<<<grid, block, SMEM_BYTES>>>(q, k, v, mask, bias, out);
}

// round 6
// speedup vs baseline: 2.0440x; 2.0440x over previous
#include <cuda_runtime.h>
#include <cuda_bf16.h>
#include <math.h>
#include <stdint.h>

#define B_   8
#define L_   1024
#define H_   8
#define D_   32
#define C_   256
#define QT   128     // query tile (per CTA)
#define KT   64      // key tile
#define NKT  (L_ / KT)
#define SCALE 0.17677669529663687f  // 1/sqrt(32)

// mask dtype mode: 0 = float32, 1 = int32, 2 = uint8
__device__ int g_mask_mode;

__global__ void detect_mask_mode(const unsigned int* m)
{
    bool all_f32 = true, all_i32 = true;
    for (int i = 0; i < 2048; ++i) {
        unsigned int w = m[i];
        if (w != 0u && w != 0x3f800000u) all_f32 = false;
        if (w != 0u && w != 1u)          all_i32 = false;
    }
    g_mask_mode = all_f32 ? 0 : (all_i32 ? 1 : 2);
}

__device__ __forceinline__ bool mask_at(const void* m, int idx, int mode)
{
    if (mode == 0) return ((const float*)m)[idx] != 0.0f;
    if (mode == 1) return ((const int*)m)[idx]   != 0;
    return ((const unsigned char*)m)[idx] != 0;
}

// mma.sync m16n8k16, bf16 inputs, f32 accumulate (D = A*B + D)
__device__ __forceinline__ void mma_bf16(float c[4],
                                         uint32_t a0, uint32_t a1, uint32_t a2, uint32_t a3,
                                         uint32_t b0, uint32_t b1)
{
    asm("mma.sync.aligned.m16n8k16.row.col.f32.bf16.bf16.f32 "
        "{%0,%1,%2,%3},{%4,%5,%6,%7},{%8,%9},{%0,%1,%2,%3};"
        : "+f"(c[0]), "+f"(c[1]), "+f"(c[2]), "+f"(c[3])
        : "r"(a0), "r"(a1), "r"(a2), "r"(a3), "r"(b0), "r"(b1));
}

// split (x,y) f32 pair into bf16x2 hi word and bf16x2 lo (residual) word.
// word layout: low 16 bits = x (even element), high 16 bits = y (odd element)
__device__ __forceinline__ void split2(float x, float y, uint32_t& hi, uint32_t& lo)
{
    uint32_t h;
    asm("cvt.rn.bf16x2.f32 %0, %1, %2;" : "=r"(h) : "f"(y), "f"(x));  // lo=x, hi=y
    float hx = __uint_as_float(h << 16);
    float hy = __uint_as_float(h & 0xffff0000u);
    float rx = x - hx, ry = y - hy;
    uint32_t l;
    asm("cvt.rn.bf16x2.f32 %0, %1, %2;" : "=r"(l) : "f"(ry), "f"(rx));
    hi = h; lo = l;
}

__global__ __launch_bounds__(256, 2)
void masked_attn_kernel(const float* __restrict__ q,
                        const float* __restrict__ k,
                        const float* __restrict__ v,
                        const void* __restrict__ mask,
                        const float* __restrict__ bias,
                        float* __restrict__ out)
{
    // padded word layouts (uint32 = bf16x2); all fragment loads conflict-free
    __shared__ uint32_t Qhi[128 * 20], Qlo[128 * 20];   // [row][kpair]
    __shared__ uint32_t Khi[64 * 20],  Klo[64 * 20];    // [key][kpair]
    __shared__ uint32_t Vthi[32 * 36], Vtlo[32 * 36];   // [ch][jpair] (transposed V)
    __shared__ float    Madd[64];

    int blk = blockIdx.x;
    int qt  = blk & 7;           // 8 q-tiles of 128
    int h   = (blk >> 3) & 7;
    int b   = blk >> 6;
    int q0  = qt * QT;

    int mode = g_mask_mode;
    int t    = threadIdx.x;
    int w    = t >> 5;
    int lane = t & 31;
    int g    = lane >> 2;        // fragment row-group / n-index
    int tq   = lane & 3;         // fragment k-pair index

    // ---- stage Q: scale, split to bf16 hi/lo, pack pairs ----
    {
        const float* qbase = q + ((size_t)(b * L_ + q0)) * C_ + h * D_;
        #pragma unroll
        for (int it = 0; it < 8; ++it) {
            int idx = t + it * 256;           // 2048 words
            int row = idx >> 4, p = idx & 15;
            float2 f = *(const float2*)&qbase[(size_t)row * C_ + 2 * p];
            uint32_t hi, lo;
            split2(f.x * SCALE, f.y * SCALE, hi, lo);
            Qhi[row * 20 + p] = hi;
            Qlo[row * 20 + p] = lo;
        }
    }
    __syncthreads();

    // ---- load Q A-fragments once (rows 16w..16w+15) ----
    uint32_t aqh[8], aql[8];   // [kt2*4 + j]
    {
        int r0 = 16 * w + g;
        #pragma unroll
        for (int kt2 = 0; kt2 < 2; ++kt2) {
            int kp = tq + 8 * kt2;
            aqh[kt2 * 4 + 0] = Qhi[r0 * 20 + kp];
            aqh[kt2 * 4 + 1] = Qhi[(r0 + 8) * 20 + kp];
            aqh[kt2 * 4 + 2] = Qhi[r0 * 20 + kp + 4];
            aqh[kt2 * 4 + 3] = Qhi[(r0 + 8) * 20 + kp + 4];
            aql[kt2 * 4 + 0] = Qlo[r0 * 20 + kp];
            aql[kt2 * 4 + 1] = Qlo[(r0 + 8) * 20 + kp];
            aql[kt2 * 4 + 2] = Qlo[r0 * 20 + kp + 4];
            aql[kt2 * 4 + 3] = Qlo[(r0 + 8) * 20 + kp + 4];
        }
    }

    float m0 = -INFINITY, m1 = -INFINITY, l0 = 0.f, l1 = 0.f;
    float cpv[4][4];   // [ch-block][frag]: c0,c1 row g / c2,c3 row g+8
    #pragma unroll
    for (int nb = 0; nb < 4; ++nb)
        #pragma unroll
        for (int i = 0; i < 4; ++i) cpv[nb][i] = 0.f;

    const int row0g = q0 + 16 * w + g;        // global q rows this lane owns
    const int row1g = row0g + 8;

    for (int kt = 0; kt < NKT; ++kt) {
        int k0 = kt * KT;
        __syncthreads();   // previous tile's K/V reads done

        // ---- stage K (split bf16 pairs) ----
        {
            const float* kbase = k + ((size_t)(b * L_ + k0)) * C_ + h * D_;
            #pragma unroll
            for (int it = 0; it < 4; ++it) {
                int idx = t + it * 256;       // 1024 words
                int key = idx >> 4, p = idx & 15;
                float2 f = *(const float2*)&kbase[(size_t)key * C_ + 2 * p];
                uint32_t hi, lo;
                split2(f.x, f.y, hi, lo);
                Khi[key * 20 + p] = hi;
                Klo[key * 20 + p] = lo;
            }
        }
        // ---- stage V transposed: Vt[ch][jpair] = {V[2jp][ch], V[2jp+1][ch]} ----
        {
            const float* vbase = v + ((size_t)(b * L_ + k0)) * C_ + h * D_;
            #pragma unroll
            for (int it = 0; it < 4; ++it) {
                int idx = t + it * 256;       // 1024 words
                int ch = idx & 31, jp = idx >> 5;
                float v0 = vbase[(size_t)(2 * jp) * C_ + ch];
                float v1 = vbase[(size_t)(2 * jp + 1) * C_ + ch];
                uint32_t hi, lo;
                split2(v0, v1, hi, lo);
                Vthi[ch * 36 + jp] = hi;
                Vtlo[ch * 36 + jp] = lo;
            }
        }
        if (t < KT)
            Madd[t] = mask_at(mask, b * L_ + k0 + t, mode) ? 0.f : -1e9f;
        __syncthreads();

        // ---- QK^T: C init = bias + mask, then 6 mma per n-block ----
        float cqk[8][4];
        #pragma unroll
        for (int nb = 0; nb < 8; ++nb) {
            int j0 = nb * 8 + 2 * tq;
            float2 md = *(const float2*)&Madd[j0];
            float2 b0 = *(const float2*)&bias[((size_t)b * L_ + row0g) * L_ + k0 + j0];
            float2 b1 = *(const float2*)&bias[((size_t)b * L_ + row1g) * L_ + k0 + j0];
            cqk[nb][0] = b0.x + md.x;
            cqk[nb][1] = b0.y + md.y;
            cqk[nb][2] = b1.x + md.x;
            cqk[nb][3] = b1.y + md.y;
        }
        #pragma unroll
        for (int nb = 0; nb < 8; ++nb) {
            int key = nb * 8 + g;
            #pragma unroll
            for (int kt2 = 0; kt2 < 2; ++kt2) {
                int kp = tq + 8 * kt2;
                uint32_t bh0 = Khi[key * 20 + kp], bh1 = Khi[key * 20 + kp + 4];
                uint32_t bl0 = Klo[key * 20 + kp], bl1 = Klo[key * 20 + kp + 4];
                const uint32_t* ah = aqh + kt2 * 4;
                const uint32_t* al = aql + kt2 * 4;
                mma_bf16(cqk[nb], ah[0], ah[1], ah[2], ah[3], bh0, bh1);
                mma_bf16(cqk[nb], ah[0], ah[1], ah[2], ah[3], bl0, bl1);
                mma_bf16(cqk[nb], al[0], al[1], al[2], al[3], bh0, bh1);
            }
        }

        // ---- online softmax (rows g16, g16+8), all in registers ----
        float mt0 = -INFINITY, mt1 = -INFINITY;
        #pragma unroll
        for (int nb = 0; nb < 8; ++nb) {
            mt0 = fmaxf(mt0, fmaxf(cqk[nb][0], cqk[nb][1]));
            mt1 = fmaxf(mt1, fmaxf(cqk[nb][2], cqk[nb][3]));
        }
        mt0 = fmaxf(mt0, __shfl_xor_sync(0xffffffffu, mt0, 1));
        mt0 = fmaxf(mt0, __shfl_xor_sync(0xffffffffu, mt0, 2));
        mt1 = fmaxf(mt1, __shfl_xor_sync(0xffffffffu, mt1, 1));
        mt1 = fmaxf(mt1, __shfl_xor_sync(0xffffffffu, mt1, 2));

        float mn0 = fmaxf(m0, mt0), mn1 = fmaxf(m1, mt1);
        float f0 = __expf(m0 - mn0), f1 = __expf(m1 - mn1);
        l0 *= f0; l1 *= f1;
        #pragma unroll
        for (int nb = 0; nb < 4; ++nb) {
            cpv[nb][0] *= f0; cpv[nb][1] *= f0;
            cpv[nb][2] *= f1; cpv[nb][3] *= f1;
        }
        #pragma unroll
        for (int nb = 0; nb < 8; ++nb) {
            cqk[nb][0] = __expf(cqk[nb][0] - mn0);
            cqk[nb][1] = __expf(cqk[nb][1] - mn0);
            cqk[nb][2] = __expf(cqk[nb][2] - mn1);
            cqk[nb][3] = __expf(cqk[nb][3] - mn1);
            l0 += cqk[nb][0] + cqk[nb][1];
            l1 += cqk[nb][2] + cqk[nb][3];
        }
        m0 = mn0; m1 = mn1;

        // ---- P*V: C-frag of QK reused directly as A-frag (hi/lo split) ----
        #pragma unroll
        for (int kk = 0; kk < 4; ++kk) {
            uint32_t ap[4], al[4];
            split2(cqk[2 * kk][0],     cqk[2 * kk][1],     ap[0], al[0]);
            split2(cqk[2 * kk][2],     cqk[2 * kk][3],     ap[1], al[1]);
            split2(cqk[2 * kk + 1][0], cqk[2 * kk + 1][1], ap[2], al[2]);
            split2(cqk[2 * kk + 1][2], cqk[2 * kk + 1][3], ap[3], al[3]);
            #pragma unroll
            for (int nb = 0; nb < 4; ++nb) {
                int ch = nb * 8 + g;
                int jp = 8 * kk + tq;
                uint32_t bh0 = Vthi[ch * 36 + jp], bh1 = Vthi[ch * 36 + jp + 4];
                uint32_t bl0 = Vtlo[ch * 36 + jp], bl1 = Vtlo[ch * 36 + jp + 4];
                mma_bf16(cpv[nb], ap[0], ap[1], ap[2], ap[3], bh0, bh1);
                mma_bf16(cpv[nb], ap[0], ap[1], ap[2], ap[3], bl0, bl1);
                mma_bf16(cpv[nb], al[0], al[1], al[2], al[3], bh0, bh1);
            }
        }
    }

    // ---- epilogue ----
    l0 += __shfl_xor_sync(0xffffffffu, l0, 1);
    l0 += __shfl_xor_sync(0xffffffffu, l0, 2);
    l1 += __shfl_xor_sync(0xffffffffu, l1, 1);
    l1 += __shfl_xor_sync(0xffffffffu, l1, 2);
    float inv0 = 1.f / l0, inv1 = 1.f / l1;

    bool act0 = mask_at(mask, b * L_ + row0g, mode);
    bool act1 = mask_at(mask, b * L_ + row1g, mode);

    #pragma unroll
    for (int nb = 0; nb < 4; ++nb) {
        int ch = nb * 8 + 2 * tq;
        float2 o0, o1;
        if (act0) {
            o0 = make_float2(cpv[nb][0] * inv0, cpv[nb][1] * inv0);
        } else {
            o0 = *(const float2*)&v[((size_t)(b * L_ + row0g)) * C_ + h * D_ + ch];
        }
        if (act1) {
            o1 = make_float2(cpv[nb][2] * inv1, cpv[nb][3] * inv1);
        } else {
            o1 = *(const float2*)&v[((size_t)(b * L_ + row1g)) * C_ + h * D_ + ch];
        }
        *(float2*)&out[((size_t)(b * L_ + row0g)) * C_ + h * D_ + ch] = o0;
        *(float2*)&out[((size_t)(b * L_ + row1g)) * C_ + h * D_ + ch] = o1;
    }
}

extern "C" void kernel_launch(void* const* d_in, const int* in_sizes, int n_in,
                              void* d_out, int out_size)
{
    const int QKV_N  = B_ * L_ * C_;
    const int BIAS_N = B_ * L_ * L_;
    const int MASK_N = B_ * L_;

    int bias_i = -1, mask_i = -1;
    int big[3]; int nbig = 0;
    for (int i = 0; i < n_in; ++i) {
        if (in_sizes[i] == BIAS_N) bias_i = i;
        else if (in_sizes[i] == MASK_N) mask_i = i;
        else if (in_sizes[i] == QKV_N && nbig < 3) big[nbig++] = i;
    }

    const float* q; const float* k; const float* v;
    if (bias_i == 0) {  // alphabetical order: bias, hard_mask, key, query, value
        k = (const float*)d_in[big[0]];
        q = (const float*)d_in[big[1]];
        v = (const float*)d_in[big[2]];
    } else {            // dict order: query, key, value, hard_mask, bias
        q = (const float*)d_in[big[0]];
        k = (const float*)d_in[big[1]];
        v = (const float*)d_in[big[2]];
    }
    const void*  mask = d_in[mask_i];
    const float* bias = (const float*)d_in[bias_i];
    float*       out  = (float*)d_out;

    detect_mask_mode<<<1, 1>>>((const unsigned int*)mask);

    dim3 grid(B_ * H_ * (L_ / QT));   // 512 blocks
    dim3 block(256);
    masked_attn_kernel<<<grid, block>>>(q, k, v, mask, bias, out);
}

// round 7
// speedup vs baseline: 2.0489x; 1.0024x over previous
#include <cuda_runtime.h>
#include <cuda_bf16.h>
#include <math.h>
#include <stdint.h>

#define B_   8
#define L_   1024
#define H_   8
#define D_   32
#define C_   256
#define QT   128     // query tile (per CTA)
#define KT   64      // key tile
#define NKT  (L_ / KT)
#define SCALE 0.17677669529663687f  // 1/sqrt(32)

// mask dtype mode: 0 = float32, 1 = int32, 2 = uint8
__device__ int g_mask_mode;

__global__ void detect_mask_mode(const unsigned int* m)
{
    bool all_f32 = true, all_i32 = true;
    for (int i = 0; i < 2048; ++i) {
        unsigned int w = m[i];
        if (w != 0u && w != 0x3f800000u) all_f32 = false;
        if (w != 0u && w != 1u)          all_i32 = false;
    }
    g_mask_mode = all_f32 ? 0 : (all_i32 ? 1 : 2);
}

__device__ __forceinline__ bool mask_at(const void* m, int idx, int mode)
{
    if (mode == 0) return ((const float*)m)[idx] != 0.0f;
    if (mode == 1) return ((const int*)m)[idx]   != 0;
    return ((const unsigned char*)m)[idx] != 0;
}

// mma.sync m16n8k16, bf16 inputs, f32 accumulate (D = A*B + D)
__device__ __forceinline__ void mma_bf16(float c[4],
                                         uint32_t a0, uint32_t a1, uint32_t a2, uint32_t a3,
                                         uint32_t b0, uint32_t b1)
{
    asm("mma.sync.aligned.m16n8k16.row.col.f32.bf16.bf16.f32 "
        "{%0,%1,%2,%3},{%4,%5,%6,%7},{%8,%9},{%0,%1,%2,%3};"
        : "+f"(c[0]), "+f"(c[1]), "+f"(c[2]), "+f"(c[3])
        : "r"(a0), "r"(a1), "r"(a2), "r"(a3), "r"(b0), "r"(b1));
}

// split (x,y) f32 pair into bf16x2 hi word and bf16x2 lo (residual) word.
__device__ __forceinline__ void split2(float x, float y, uint32_t& hi, uint32_t& lo)
{
    uint32_t h;
    asm("cvt.rn.bf16x2.f32 %0, %1, %2;" : "=r"(h) : "f"(y), "f"(x));  // lo=x, hi=y
    float hx = __uint_as_float(h << 16);
    float hy = __uint_as_float(h & 0xffff0000u);
    float rx = x - hx, ry = y - hy;
    uint32_t l;
    asm("cvt.rn.bf16x2.f32 %0, %1, %2;" : "=r"(l) : "f"(ry), "f"(rx));
    hi = h; lo = l;
}

__global__ __launch_bounds__(256, 2)
void masked_attn_kernel(const float* __restrict__ q,
                        const float* __restrict__ k,
                        const float* __restrict__ v,
                        const void* __restrict__ mask,
                        const float* __restrict__ bias,
                        float* __restrict__ out)
{
    __shared__ uint32_t Qhi[128 * 20], Qlo[128 * 20];   // [row][kpair]
    __shared__ uint32_t Khi[64 * 20],  Klo[64 * 20];    // [key][kpair]
    __shared__ uint32_t Vthi[32 * 36], Vtlo[32 * 36];   // [ch][jpair] (transposed V)
    __shared__ float    Madd[64];

    int blk = blockIdx.x;
    int qt  = blk & 7;           // 8 q-tiles of 128
    int h   = (blk >> 3) & 7;
    int b   = blk >> 6;
    int q0  = qt * QT;

    int mode = g_mask_mode;
    int t    = threadIdx.x;
    int w    = t >> 5;
    int lane = t & 31;
    int g    = lane >> 2;        // fragment row-group / n-index
    int tq   = lane & 3;         // fragment k-pair index

    // staging index precompute (K: float4 granularity; V: float2 over row pairs)
    // K: idx4 in [0,512): key = idx4>>3, kpair base = (idx4&7)*2
    // V: idx2 in [0,512): jp = idx2>>4, ch base = (idx2&15)*2
    const float* kvm_base = k;   // silence unused warnings pattern (not used)

    // ---- stage Q: scale, split to bf16 hi/lo, pack pairs ----
    {
        const float* qbase = q + ((size_t)(b * L_ + q0)) * C_ + h * D_;
        #pragma unroll
        for (int it = 0; it < 8; ++it) {
            int idx = t + it * 256;           // 2048 words
            int row = idx >> 4, p = idx & 15;
            float2 f = *(const float2*)&qbase[(size_t)row * C_ + 2 * p];
            uint32_t hi, lo;
            split2(f.x * SCALE, f.y * SCALE, hi, lo);
            Qhi[row * 20 + p] = hi;
            Qlo[row * 20 + p] = lo;
        }
    }

    // ---- prologue: stage K/V/mask tile 0 ----
    {
        const float* kbase = k + ((size_t)(b * L_)) * C_ + h * D_;
        const float* vbase = v + ((size_t)(b * L_)) * C_ + h * D_;
        #pragma unroll
        for (int it = 0; it < 2; ++it) {
            int idx4 = t + it * 256;
            int key = idx4 >> 3, p4 = (idx4 & 7) * 2;
            float4 f = *(const float4*)&kbase[(size_t)key * C_ + 2 * p4];
            uint32_t h0, l0w, h1, l1w;
            split2(f.x, f.y, h0, l0w);
            split2(f.z, f.w, h1, l1w);
            Khi[key * 20 + p4]     = h0;  Klo[key * 20 + p4]     = l0w;
            Khi[key * 20 + p4 + 1] = h1;  Klo[key * 20 + p4 + 1] = l1w;
        }
        #pragma unroll
        for (int it = 0; it < 2; ++it) {
            int idx2 = t + it * 256;
            int jp = idx2 >> 4, ch2 = (idx2 & 15) * 2;
            float2 a = *(const float2*)&vbase[(size_t)(2 * jp) * C_ + ch2];
            float2 c = *(const float2*)&vbase[(size_t)(2 * jp + 1) * C_ + ch2];
            uint32_t h0, l0w, h1, l1w;
            split2(a.x, c.x, h0, l0w);
            split2(a.y, c.y, h1, l1w);
            Vthi[ch2 * 36 + jp]       = h0;  Vtlo[ch2 * 36 + jp]       = l0w;
            Vthi[(ch2 + 1) * 36 + jp] = h1;  Vtlo[(ch2 + 1) * 36 + jp] = l1w;
        }
        if (t < KT)
            Madd[t] = mask_at(mask, b * L_ + t, mode) ? 0.f : -1e9f;
    }
    __syncthreads();

    // ---- load Q A-fragments once (rows 16w..16w+15) ----
    uint32_t aqh[8], aql[8];
    {
        int r0 = 16 * w + g;
        #pragma unroll
        for (int kt2 = 0; kt2 < 2; ++kt2) {
            int kp = tq + 8 * kt2;
            aqh[kt2 * 4 + 0] = Qhi[r0 * 20 + kp];
            aqh[kt2 * 4 + 1] = Qhi[(r0 + 8) * 20 + kp];
            aqh[kt2 * 4 + 2] = Qhi[r0 * 20 + kp + 4];
            aqh[kt2 * 4 + 3] = Qhi[(r0 + 8) * 20 + kp + 4];
            aql[kt2 * 4 + 0] = Qlo[r0 * 20 + kp];
            aql[kt2 * 4 + 1] = Qlo[(r0 + 8) * 20 + kp];
            aql[kt2 * 4 + 2] = Qlo[r0 * 20 + kp + 4];
            aql[kt2 * 4 + 3] = Qlo[(r0 + 8) * 20 + kp + 4];
        }
    }

    float m0 = -INFINITY, m1 = -INFINITY, l0 = 0.f, l1 = 0.f;
    float cpv[4][4];
    #pragma unroll
    for (int nb = 0; nb < 4; ++nb)
        #pragma unroll
        for (int i = 0; i < 4; ++i) cpv[nb][i] = 0.f;

    const int row0g = q0 + 16 * w + g;
    const int row1g = row0g + 8;

    for (int kt = 0; kt < NKT; ++kt) {
        int k0n = (kt + 1) * KT;
        bool pf = (kt + 1) < NKT;

        // ---- prefetch next tile's K/V/mask into registers ----
        float4 kpre[2];
        float2 vpa[2], vpb[2];
        float  maddpre = 0.f;
        if (pf) {
            const float* kbase_n = k + ((size_t)(b * L_ + k0n)) * C_ + h * D_;
            const float* vbase_n = v + ((size_t)(b * L_ + k0n)) * C_ + h * D_;
            #pragma unroll
            for (int it = 0; it < 2; ++it) {
                int idx4 = t + it * 256;
                int key = idx4 >> 3, p4 = (idx4 & 7) * 2;
                kpre[it] = *(const float4*)&kbase_n[(size_t)key * C_ + 2 * p4];
            }
            #pragma unroll
            for (int it = 0; it < 2; ++it) {
                int idx2 = t + it * 256;
                int jp = idx2 >> 4, ch2 = (idx2 & 15) * 2;
                vpa[it] = *(const float2*)&vbase_n[(size_t)(2 * jp) * C_ + ch2];
                vpb[it] = *(const float2*)&vbase_n[(size_t)(2 * jp + 1) * C_ + ch2];
            }
            if (t < KT)
                maddpre = mask_at(mask, b * L_ + k0n + t, mode) ? 0.f : -1e9f;
        }

        int k0 = kt * KT;

        // ---- QK^T: C init = bias + mask ----
        float cqk[8][4];
        #pragma unroll
        for (int nb = 0; nb < 8; ++nb) {
            int j0 = nb * 8 + 2 * tq;
            float2 md = *(const float2*)&Madd[j0];
            float2 b0 = *(const float2*)&bias[((size_t)b * L_ + row0g) * L_ + k0 + j0];
            float2 b1 = *(const float2*)&bias[((size_t)b * L_ + row1g) * L_ + k0 + j0];
            cqk[nb][0] = b0.x + md.x;
            cqk[nb][1] = b0.y + md.y;
            cqk[nb][2] = b1.x + md.x;
            cqk[nb][3] = b1.y + md.y;
        }
        #pragma unroll
        for (int nb = 0; nb < 8; ++nb) {
            int key = nb * 8 + g;
            #pragma unroll
            for (int kt2 = 0; kt2 < 2; ++kt2) {
                int kp = tq + 8 * kt2;
                uint32_t bh0 = Khi[key * 20 + kp], bh1 = Khi[key * 20 + kp + 4];
                uint32_t bl0 = Klo[key * 20 + kp], bl1 = Klo[key * 20 + kp + 4];
                const uint32_t* ah = aqh + kt2 * 4;
                const uint32_t* al = aql + kt2 * 4;
                mma_bf16(cqk[nb], ah[0], ah[1], ah[2], ah[3], bh0, bh1);
                mma_bf16(cqk[nb], ah[0], ah[1], ah[2], ah[3], bl0, bl1);
                mma_bf16(cqk[nb], al[0], al[1], al[2], al[3], bh0, bh1);
            }
        }

        // ---- online softmax (register-resident) ----
        float mt0 = -INFINITY, mt1 = -INFINITY;
        #pragma unroll
        for (int nb = 0; nb < 8; ++nb) {
            mt0 = fmaxf(mt0, fmaxf(cqk[nb][0], cqk[nb][1]));
            mt1 = fmaxf(mt1, fmaxf(cqk[nb][2], cqk[nb][3]));
        }
        mt0 = fmaxf(mt0, __shfl_xor_sync(0xffffffffu, mt0, 1));
        mt0 = fmaxf(mt0, __shfl_xor_sync(0xffffffffu, mt0, 2));
        mt1 = fmaxf(mt1, __shfl_xor_sync(0xffffffffu, mt1, 1));
        mt1 = fmaxf(mt1, __shfl_xor_sync(0xffffffffu, mt1, 2));

        float mn0 = fmaxf(m0, mt0), mn1 = fmaxf(m1, mt1);
        float f0 = __expf(m0 - mn0), f1 = __expf(m1 - mn1);
        l0 *= f0; l1 *= f1;
        #pragma unroll
        for (int nb = 0; nb < 4; ++nb) {
            cpv[nb][0] *= f0; cpv[nb][1] *= f0;
            cpv[nb][2] *= f1; cpv[nb][3] *= f1;
        }
        #pragma unroll
        for (int nb = 0; nb < 8; ++nb) {
            cqk[nb][0] = __expf(cqk[nb][0] - mn0);
            cqk[nb][1] = __expf(cqk[nb][1] - mn0);
            cqk[nb][2] = __expf(cqk[nb][2] - mn1);
            cqk[nb][3] = __expf(cqk[nb][3] - mn1);
            l0 += cqk[nb][0] + cqk[nb][1];
            l1 += cqk[nb][2] + cqk[nb][3];
        }
        m0 = mn0; m1 = mn1;

        // ---- P*V ----
        #pragma unroll
        for (int kk = 0; kk < 4; ++kk) {
            uint32_t ap[4], al[4];
            split2(cqk[2 * kk][0],     cqk[2 * kk][1],     ap[0], al[0]);
            split2(cqk[2 * kk][2],     cqk[2 * kk][3],     ap[1], al[1]);
            split2(cqk[2 * kk + 1][0], cqk[2 * kk + 1][1], ap[2], al[2]);
            split2(cqk[2 * kk + 1][2], cqk[2 * kk + 1][3], ap[3], al[3]);
            #pragma unroll
            for (int nb = 0; nb < 4; ++nb) {
                int ch = nb * 8 + g;
                int jp = 8 * kk + tq;
                uint32_t bh0 = Vthi[ch * 36 + jp], bh1 = Vthi[ch * 36 + jp + 4];
                uint32_t bl0 = Vtlo[ch * 36 + jp], bl1 = Vtlo[ch * 36 + jp + 4];
                mma_bf16(cpv[nb], ap[0], ap[1], ap[2], ap[3], bh0, bh1);
                mma_bf16(cpv[nb], ap[0], ap[1], ap[2], ap[3], bl0, bl1);
                mma_bf16(cpv[nb], al[0], al[1], al[2], al[3], bh0, bh1);
            }
        }

        __syncthreads();   // all warps done reading tile kt smem

        // ---- split + STS the prefetched tile kt+1 ----
        if (pf) {
            #pragma unroll
            for (int it = 0; it < 2; ++it) {
                int idx4 = t + it * 256;
                int key = idx4 >> 3, p4 = (idx4 & 7) * 2;
                uint32_t h0, l0w, h1, l1w;
                split2(kpre[it].x, kpre[it].y, h0, l0w);
                split2(kpre[it].z, kpre[it].w, h1, l1w);
                Khi[key * 20 + p4]     = h0;  Klo[key * 20 + p4]     = l0w;
                Khi[key * 20 + p4 + 1] = h1;  Klo[key * 20 + p4 + 1] = l1w;
            }
            #pragma unroll
            for (int it = 0; it < 2; ++it) {
                int idx2 = t + it * 256;
                int jp = idx2 >> 4, ch2 = (idx2 & 15) * 2;
                uint32_t h0, l0w, h1, l1w;
                split2(vpa[it].x, vpb[it].x, h0, l0w);
                split2(vpa[it].y, vpb[it].y, h1, l1w);
                Vthi[ch2 * 36 + jp]       = h0;  Vtlo[ch2 * 36 + jp]       = l0w;
                Vthi[(ch2 + 1) * 36 + jp] = h1;  Vtlo[(ch2 + 1) * 36 + jp] = l1w;
            }
            if (t < KT) Madd[t] = maddpre;
            __syncthreads();
        }
    }

    // ---- epilogue ----
    l0 += __shfl_xor_sync(0xffffffffu, l0, 1);
    l0 += __shfl_xor_sync(0xffffffffu, l0, 2);
    l1 += __shfl_xor_sync(0xffffffffu, l1, 1);
    l1 += __shfl_xor_sync(0xffffffffu, l1, 2);
    float inv0 = 1.f / l0, inv1 = 1.f / l1;

    bool act0 = mask_at(mask, b * L_ + row0g, mode);
    bool act1 = mask_at(mask, b * L_ + row1g, mode);

    #pragma unroll
    for (int nb = 0; nb < 4; ++nb) {
        int ch = nb * 8 + 2 * tq;
        float2 o0, o1;
        if (act0) {
            o0 = make_float2(cpv[nb][0] * inv0, cpv[nb][1] * inv0);
        } else {
            o0 = *(const float2*)&v[((size_t)(b * L_ + row0g)) * C_ + h * D_ + ch];
        }
        if (act1) {
            o1 = make_float2(cpv[nb][2] * inv1, cpv[nb][3] * inv1);
        } else {
            o1 = *(const float2*)&v[((size_t)(b * L_ + row1g)) * C_ + h * D_ + ch];
        }
        *(float2*)&out[((size_t)(b * L_ + row0g)) * C_ + h * D_ + ch] = o0;
        *(float2*)&out[((size_t)(b * L_ + row1g)) * C_ + h * D_ + ch] = o1;
    }
    (void)kvm_base;
}

extern "C" void kernel_launch(void* const* d_in, const int* in_sizes, int n_in,
                              void* d_out, int out_size)
{
    const int QKV_N  = B_ * L_ * C_;
    const int BIAS_N = B_ * L_ * L_;
    const int MASK_N = B_ * L_;

    int bias_i = -1, mask_i = -1;
    int big[3]; int nbig = 0;
    for (int i = 0; i < n_in; ++i) {
        if (in_sizes[i] == BIAS_N) bias_i = i;
        else if (in_sizes[i] == MASK_N) mask_i = i;
        else if (in_sizes[i] == QKV_N && nbig < 3) big[nbig++] = i;
    }

    const float* q; const float* k; const float* v;
    if (bias_i == 0) {  // alphabetical order: bias, hard_mask, key, query, value
        k = (const float*)d_in[big[0]];
        q = (const float*)d_in[big[1]];
        v = (const float*)d_in[big[2]];
    } else {            // dict order: query, key, value, hard_mask, bias
        q = (const float*)d_in[big[0]];
        k = (const float*)d_in[big[1]];
        v = (const float*)d_in[big[2]];
    }
    const void*  mask = d_in[mask_i];
    const float* bias = (const float*)d_in[bias_i];
    float*       out  = (float*)d_out;

    detect_mask_mode<<<1, 1>>>((const unsigned int*)mask);

    dim3 grid(B_ * H_ * (L_ / QT));   // 512 blocks
    dim3 block(256);
    masked_attn_kernel<<<grid, block>>>(q, k, v, mask, bias, out);
}

// round 8
// speedup vs baseline: 2.1442x; 1.0465x over previous
#include <cuda_runtime.h>
#include <cuda_bf16.h>
#include <math.h>
#include <stdint.h>

#define B_   8
#define L_   1024
#define H_   8
#define D_   32
#define C_   256
#define QT   128
#define KT   64
#define NKT  (L_ / KT)
#define SCALE 0.17677669529663687f  // 1/sqrt(32)

// dynamic smem word offsets (uint32 words)
#define QHI_W    0                     // [128*20] prologue only
#define QLO_W    2560                  // [128*20] prologue only
#define RAWK_W   0                     // overlay: RawK[64][36] f32 (2304 w)
#define RAWV_W   2560                  // overlay: RawV[64][36] f32 (2304 w)
#define KHI_W    5120                  // [64*20]
#define KLO_W    6400                  // [64*20]
#define VTHI_W   7680                  // [32*36]
#define VTLO_W   8832                  // [32*36]
#define BIAS_W   9984                  // 2 x [128*68] f32
#define BIAS_STRIDE_W 8704
#define MADD_W   (BIAS_W + 2*BIAS_STRIDE_W)   // 27392
#define SMEM_W   (MADD_W + 64)                // 27456 words
#define SMEM_BYTES (SMEM_W * 4)               // 109824 B

__device__ int g_mask_mode;

__global__ void detect_mask_mode(const unsigned int* m)
{
    bool all_f32 = true, all_i32 = true;
    for (int i = 0; i < 2048; ++i) {
        unsigned int w = m[i];
        if (w != 0u && w != 0x3f800000u) all_f32 = false;
        if (w != 0u && w != 1u)          all_i32 = false;
    }
    g_mask_mode = all_f32 ? 0 : (all_i32 ? 1 : 2);
}

__device__ __forceinline__ bool mask_at(const void* m, int idx, int mode)
{
    if (mode == 0) return ((const float*)m)[idx] != 0.0f;
    if (mode == 1) return ((const int*)m)[idx]   != 0;
    return ((const unsigned char*)m)[idx] != 0;
}

__device__ __forceinline__ void mma_bf16(float c[4],
                                         uint32_t a0, uint32_t a1, uint32_t a2, uint32_t a3,
                                         uint32_t b0, uint32_t b1)
{
    asm("mma.sync.aligned.m16n8k16.row.col.f32.bf16.bf16.f32 "
        "{%0,%1,%2,%3},{%4,%5,%6,%7},{%8,%9},{%0,%1,%2,%3};"
        : "+f"(c[0]), "+f"(c[1]), "+f"(c[2]), "+f"(c[3])
        : "r"(a0), "r"(a1), "r"(a2), "r"(a3), "r"(b0), "r"(b1));
}

__device__ __forceinline__ void split2(float x, float y, uint32_t& hi, uint32_t& lo)
{
    uint32_t h;
    asm("cvt.rn.bf16x2.f32 %0, %1, %2;" : "=r"(h) : "f"(y), "f"(x));  // lo=x, hi=y
    float hx = __uint_as_float(h << 16);
    float hy = __uint_as_float(h & 0xffff0000u);
    float rx = x - hx, ry = y - hy;
    uint32_t l;
    asm("cvt.rn.bf16x2.f32 %0, %1, %2;" : "=r"(l) : "f"(ry), "f"(rx));
    hi = h; lo = l;
}

__device__ __forceinline__ void cp16(uint32_t dst, const void* src)
{
    asm volatile("cp.async.cg.shared.global [%0], [%1], 16;" :: "r"(dst), "l"(src) : "memory");
}
__device__ __forceinline__ void cp_commit()
{
    asm volatile("cp.async.commit_group;" ::: "memory");
}
template<int N> __device__ __forceinline__ void cp_wait()
{
    asm volatile("cp.async.wait_group %0;" :: "n"(N) : "memory");
}

__global__ __launch_bounds__(256, 2)
void masked_attn_kernel(const float* __restrict__ q,
                        const float* __restrict__ k,
                        const float* __restrict__ v,
                        const void* __restrict__ mask,
                        const float* __restrict__ bias,
                        float* __restrict__ out)
{
    extern __shared__ uint32_t smw[];
    uint32_t* Qhi  = smw + QHI_W;
    uint32_t* Qlo  = smw + QLO_W;
    float*    RawK = (float*)(smw + RAWK_W);
    float*    RawV = (float*)(smw + RAWV_W);
    uint32_t* Khi  = smw + KHI_W;
    uint32_t* Klo  = smw + KLO_W;
    uint32_t* Vthi = smw + VTHI_W;
    uint32_t* Vtlo = smw + VTLO_W;
    float*    BiasS= (float*)(smw + BIAS_W);
    float*    Madd = (float*)(smw + MADD_W);
    uint32_t  smem_u32 = (uint32_t)__cvta_generic_to_shared(smw);

    int blk = blockIdx.x;
    int qt  = blk & 7;
    int h   = (blk >> 3) & 7;
    int b   = blk >> 6;
    int q0  = qt * QT;

    int mode = g_mask_mode;
    int t    = threadIdx.x;
    int w    = t >> 5;
    int lane = t & 31;
    int g    = lane >> 2;
    int tq   = lane & 3;

    const float* kbase0 = k + ((size_t)(b * L_)) * C_ + h * D_;
    const float* vbase0 = v + ((size_t)(b * L_)) * C_ + h * D_;

    // cp.async index decomposition (fixed per thread)
    // bias: it<8: idx=t+256it, row=idx>>4, c4=(idx&15)*4
    // raw : it<2: idx4=t+256it, key=idx4>>3, quad=idx4&7

    // ---- issue bias(0) into buf 0 ----
    {
        const float* bb = bias + ((size_t)b * L_ + q0) * L_;   // + row*L + col
        #pragma unroll
        for (int it = 0; it < 8; ++it) {
            int idx = t + it * 256;
            int row = idx >> 4, c4 = (idx & 15) * 4;
            cp16(smem_u32 + (BIAS_W + row * 68 + c4) * 4,
                 bb + (size_t)row * L_ + c4);
        }
        cp_commit();   // group: bias0
    }

    // ---- stage Q (LDG, split, STS) ----
    {
        const float* qbase = q + ((size_t)(b * L_ + q0)) * C_ + h * D_;
        #pragma unroll
        for (int it = 0; it < 8; ++it) {
            int idx = t + it * 256;
            int row = idx >> 4, p = idx & 15;
            float2 f = *(const float2*)&qbase[(size_t)row * C_ + 2 * p];
            uint32_t hi, lo;
            split2(f.x * SCALE, f.y * SCALE, hi, lo);
            Qhi[row * 20 + p] = hi;
            Qlo[row * 20 + p] = lo;
        }
    }
    __syncthreads();

    // ---- load Q A-fragments ----
    uint32_t aqh[8], aql[8];
    {
        int r0 = 16 * w + g;
        #pragma unroll
        for (int kt2 = 0; kt2 < 2; ++kt2) {
            int kp = tq + 8 * kt2;
            aqh[kt2 * 4 + 0] = Qhi[r0 * 20 + kp];
            aqh[kt2 * 4 + 1] = Qhi[(r0 + 8) * 20 + kp];
            aqh[kt2 * 4 + 2] = Qhi[r0 * 20 + kp + 4];
            aqh[kt2 * 4 + 3] = Qhi[(r0 + 8) * 20 + kp + 4];
            aql[kt2 * 4 + 0] = Qlo[r0 * 20 + kp];
            aql[kt2 * 4 + 1] = Qlo[(r0 + 8) * 20 + kp];
            aql[kt2 * 4 + 2] = Qlo[r0 * 20 + kp + 4];
            aql[kt2 * 4 + 3] = Qlo[(r0 + 8) * 20 + kp + 4];
        }
    }
    __syncthreads();   // Q region free -> raw overlay

    // ---- issue raw K/V (tile 0) ----
    #pragma unroll
    for (int it = 0; it < 2; ++it) {
        int idx4 = t + it * 256;
        int key = idx4 >> 3, quad = idx4 & 7;
        cp16(smem_u32 + (RAWK_W + key * 36 + quad * 4) * 4,
             kbase0 + (size_t)key * C_ + quad * 4);
        cp16(smem_u32 + (RAWV_W + key * 36 + quad * 4) * 4,
             vbase0 + (size_t)key * C_ + quad * 4);
    }
    cp_commit();   // group: raw0
    cp_wait<0>();  // bias0 + raw0 done
    __syncthreads();

    // ---- split raw(0) -> bf16 tiles; Madd(0) ----
    {
        #pragma unroll
        for (int it = 0; it < 2; ++it) {
            int idx4 = t + it * 256;
            int key = idx4 >> 3, quad = idx4 & 7;
            float4 f = *(const float4*)&RawK[key * 36 + quad * 4];
            uint32_t h0, l0w, h1, l1w;
            split2(f.x, f.y, h0, l0w);
            split2(f.z, f.w, h1, l1w);
            int p4 = quad * 2;
            Khi[key * 20 + p4]     = h0;  Klo[key * 20 + p4]     = l0w;
            Khi[key * 20 + p4 + 1] = h1;  Klo[key * 20 + p4 + 1] = l1w;
        }
        #pragma unroll
        for (int it = 0; it < 2; ++it) {
            int idx2 = t + it * 256;
            int jp = idx2 >> 4, ch2 = (idx2 & 15) * 2;
            float2 a = *(const float2*)&RawV[(2 * jp) * 36 + ch2];
            float2 c = *(const float2*)&RawV[(2 * jp + 1) * 36 + ch2];
            uint32_t h0, l0w, h1, l1w;
            split2(a.x, c.x, h0, l0w);
            split2(a.y, c.y, h1, l1w);
            Vthi[ch2 * 36 + jp]       = h0;  Vtlo[ch2 * 36 + jp]       = l0w;
            Vthi[(ch2 + 1) * 36 + jp] = h1;  Vtlo[(ch2 + 1) * 36 + jp] = l1w;
        }
        if (t < KT)
            Madd[t] = mask_at(mask, b * L_ + t, mode) ? 0.f : -1e9f;
    }
    __syncthreads();

    // ---- issue raw(1) ----
    #pragma unroll
    for (int it = 0; it < 2; ++it) {
        int idx4 = t + it * 256;
        int key = idx4 >> 3, quad = idx4 & 7;
        cp16(smem_u32 + (RAWK_W + key * 36 + quad * 4) * 4,
             kbase0 + (size_t)(KT + key) * C_ + quad * 4);
        cp16(smem_u32 + (RAWV_W + key * 36 + quad * 4) * 4,
             vbase0 + (size_t)(KT + key) * C_ + quad * 4);
    }
    cp_commit();   // group: raw1

    float m0 = -INFINITY, m1 = -INFINITY, l0 = 0.f, l1 = 0.f;
    float cpv[4][4];
    #pragma unroll
    for (int nb = 0; nb < 4; ++nb)
        #pragma unroll
        for (int i = 0; i < 4; ++i) cpv[nb][i] = 0.f;

    const int row0g = q0 + 16 * w + g;
    const int row1g = row0g + 8;
    const int rloc  = 16 * w + g;          // local row in bias smem

    for (int kt = 0; kt < NKT; ++kt) {
        bool pf = (kt + 1) < NKT;
        float maddpre = 0.f;

        // ---- issue bias(kt+1); prefetch mask(kt+1) ----
        if (pf) {
            int buf = (kt + 1) & 1;
            const float* bb = bias + ((size_t)b * L_ + q0) * L_ + (kt + 1) * KT;
            #pragma unroll
            for (int it = 0; it < 8; ++it) {
                int idx = t + it * 256;
                int row = idx >> 4, c4 = (idx & 15) * 4;
                cp16(smem_u32 + (BIAS_W + buf * BIAS_STRIDE_W + row * 68 + c4) * 4,
                     bb + (size_t)row * L_ + c4);
            }
            cp_commit();
            if (t < KT)
                maddpre = mask_at(mask, b * L_ + (kt + 1) * KT + t, mode) ? 0.f : -1e9f;
        }

        // ---- QK^T: C init = bias(smem) + mask ----
        const float* bs = BiasS + (kt & 1) * BIAS_STRIDE_W;
        float cqk[8][4];
        #pragma unroll
        for (int nb = 0; nb < 8; ++nb) {
            int j0 = nb * 8 + 2 * tq;
            float2 md = *(const float2*)&Madd[j0];
            float2 b0 = *(const float2*)&bs[rloc * 68 + j0];
            float2 b1 = *(const float2*)&bs[(rloc + 8) * 68 + j0];
            cqk[nb][0] = b0.x + md.x;
            cqk[nb][1] = b0.y + md.y;
            cqk[nb][2] = b1.x + md.x;
            cqk[nb][3] = b1.y + md.y;
        }
        #pragma unroll
        for (int nb = 0; nb < 8; ++nb) {
            int key = nb * 8 + g;
            #pragma unroll
            for (int kt2 = 0; kt2 < 2; ++kt2) {
                int kp = tq + 8 * kt2;
                uint32_t bh0 = Khi[key * 20 + kp], bh1 = Khi[key * 20 + kp + 4];
                uint32_t bl0 = Klo[key * 20 + kp], bl1 = Klo[key * 20 + kp + 4];
                const uint32_t* ah = aqh + kt2 * 4;
                const uint32_t* al = aql + kt2 * 4;
                mma_bf16(cqk[nb], ah[0], ah[1], ah[2], ah[3], bh0, bh1);
                mma_bf16(cqk[nb], ah[0], ah[1], ah[2], ah[3], bl0, bl1);
                mma_bf16(cqk[nb], al[0], al[1], al[2], al[3], bh0, bh1);
            }
        }

        // ---- online softmax ----
        float mt0 = -INFINITY, mt1 = -INFINITY;
        #pragma unroll
        for (int nb = 0; nb < 8; ++nb) {
            mt0 = fmaxf(mt0, fmaxf(cqk[nb][0], cqk[nb][1]));
            mt1 = fmaxf(mt1, fmaxf(cqk[nb][2], cqk[nb][3]));
        }
        mt0 = fmaxf(mt0, __shfl_xor_sync(0xffffffffu, mt0, 1));
        mt0 = fmaxf(mt0, __shfl_xor_sync(0xffffffffu, mt0, 2));
        mt1 = fmaxf(mt1, __shfl_xor_sync(0xffffffffu, mt1, 1));
        mt1 = fmaxf(mt1, __shfl_xor_sync(0xffffffffu, mt1, 2));

        float mn0 = fmaxf(m0, mt0), mn1 = fmaxf(m1, mt1);
        float f0 = __expf(m0 - mn0), f1 = __expf(m1 - mn1);
        l0 *= f0; l1 *= f1;
        #pragma unroll
        for (int nb = 0; nb < 4; ++nb) {
            cpv[nb][0] *= f0; cpv[nb][1] *= f0;
            cpv[nb][2] *= f1; cpv[nb][3] *= f1;
        }
        #pragma unroll
        for (int nb = 0; nb < 8; ++nb) {
            cqk[nb][0] = __expf(cqk[nb][0] - mn0);
            cqk[nb][1] = __expf(cqk[nb][1] - mn0);
            cqk[nb][2] = __expf(cqk[nb][2] - mn1);
            cqk[nb][3] = __expf(cqk[nb][3] - mn1);
            l0 += cqk[nb][0] + cqk[nb][1];
            l1 += cqk[nb][2] + cqk[nb][3];
        }
        m0 = mn0; m1 = mn1;

        // ---- P*V ----
        #pragma unroll
        for (int kk = 0; kk < 4; ++kk) {
            uint32_t ap[4], al[4];
            split2(cqk[2 * kk][0],     cqk[2 * kk][1],     ap[0], al[0]);
            split2(cqk[2 * kk][2],     cqk[2 * kk][3],     ap[1], al[1]);
            split2(cqk[2 * kk + 1][0], cqk[2 * kk + 1][1], ap[2], al[2]);
            split2(cqk[2 * kk + 1][2], cqk[2 * kk + 1][3], ap[3], al[3]);
            #pragma unroll
            for (int nb = 0; nb < 4; ++nb) {
                int ch = nb * 8 + g;
                int jp = 8 * kk + tq;
                uint32_t bh0 = Vthi[ch * 36 + jp], bh1 = Vthi[ch * 36 + jp + 4];
                uint32_t bl0 = Vtlo[ch * 36 + jp], bl1 = Vtlo[ch * 36 + jp + 4];
                mma_bf16(cpv[nb], ap[0], ap[1], ap[2], ap[3], bh0, bh1);
                mma_bf16(cpv[nb], ap[0], ap[1], ap[2], ap[3], bl0, bl1);
                mma_bf16(cpv[nb], al[0], al[1], al[2], al[3], bh0, bh1);
            }
        }

        // ---- pipeline turn: split raw(kt+1), issue raw(kt+2) ----
        if (pf) {
            cp_wait<0>();      // raw(kt+1) + bias(kt+1) complete
            __syncthreads();   // visibility of all threads' copies; Ksplit free
            #pragma unroll
            for (int it = 0; it < 2; ++it) {
                int idx4 = t + it * 256;
                int key = idx4 >> 3, quad = idx4 & 7;
                float4 f = *(const float4*)&RawK[key * 36 + quad * 4];
                uint32_t h0, l0w, h1, l1w;
                split2(f.x, f.y, h0, l0w);
                split2(f.z, f.w, h1, l1w);
                int p4 = quad * 2;
                Khi[key * 20 + p4]     = h0;  Klo[key * 20 + p4]     = l0w;
                Khi[key * 20 + p4 + 1] = h1;  Klo[key * 20 + p4 + 1] = l1w;
            }
            #pragma unroll
            for (int it = 0; it < 2; ++it) {
                int idx2 = t + it * 256;
                int jp = idx2 >> 4, ch2 = (idx2 & 15) * 2;
                float2 a = *(const float2*)&RawV[(2 * jp) * 36 + ch2];
                float2 c = *(const float2*)&RawV[(2 * jp + 1) * 36 + ch2];
                uint32_t h0, l0w, h1, l1w;
                split2(a.x, c.x, h0, l0w);
                split2(a.y, c.y, h1, l1w);
                Vthi[ch2 * 36 + jp]       = h0;  Vtlo[ch2 * 36 + jp]       = l0w;
                Vthi[(ch2 + 1) * 36 + jp] = h1;  Vtlo[(ch2 + 1) * 36 + jp] = l1w;
            }
            if (t < KT) Madd[t] = maddpre;
            __syncthreads();   // splits done; raw buffer free for kt+2
            if (kt + 2 < NKT) {
                #pragma unroll
                for (int it = 0; it < 2; ++it) {
                    int idx4 = t + it * 256;
                    int key = idx4 >> 3, quad = idx4 & 7;
                    cp16(smem_u32 + (RAWK_W + key * 36 + quad * 4) * 4,
                         kbase0 + (size_t)((kt + 2) * KT + key) * C_ + quad * 4);
                    cp16(smem_u32 + (RAWV_W + key * 36 + quad * 4) * 4,
                         vbase0 + (size_t)((kt + 2) * KT + key) * C_ + quad * 4);
                }
                cp_commit();
            }
        }
    }

    // ---- epilogue ----
    l0 += __shfl_xor_sync(0xffffffffu, l0, 1);
    l0 += __shfl_xor_sync(0xffffffffu, l0, 2);
    l1 += __shfl_xor_sync(0xffffffffu, l1, 1);
    l1 += __shfl_xor_sync(0xffffffffu, l1, 2);
    float inv0 = 1.f / l0, inv1 = 1.f / l1;

    bool act0 = mask_at(mask, b * L_ + row0g, mode);
    bool act1 = mask_at(mask, b * L_ + row1g, mode);

    #pragma unroll
    for (int nb = 0; nb < 4; ++nb) {
        int ch = nb * 8 + 2 * tq;
        float2 o0, o1;
        if (act0) {
            o0 = make_float2(cpv[nb][0] * inv0, cpv[nb][1] * inv0);
        } else {
            o0 = *(const float2*)&v[((size_t)(b * L_ + row0g)) * C_ + h * D_ + ch];
        }
        if (act1) {
            o1 = make_float2(cpv[nb][2] * inv1, cpv[nb][3] * inv1);
        } else {
            o1 = *(const float2*)&v[((size_t)(b * L_ + row1g)) * C_ + h * D_ + ch];
        }
        *(float2*)&out[((size_t)(b * L_ + row0g)) * C_ + h * D_ + ch] = o0;
        *(float2*)&out[((size_t)(b * L_ + row1g)) * C_ + h * D_ + ch] = o1;
    }
}

extern "C" void kernel_launch(void* const* d_in, const int* in_sizes, int n_in,
                              void* d_out, int out_size)
{
    const int QKV_N  = B_ * L_ * C_;
    const int BIAS_N = B_ * L_ * L_;
    const int MASK_N = B_ * L_;

    int bias_i = -1, mask_i = -1;
    int big[3]; int nbig = 0;
    for (int i = 0; i < n_in; ++i) {
        if (in_sizes[i] == BIAS_N) bias_i = i;
        else if (in_sizes[i] == MASK_N) mask_i = i;
        else if (in_sizes[i] == QKV_N && nbig < 3) big[nbig++] = i;
    }

    const float* q; const float* k; const float* v;
    if (bias_i == 0) {  // alphabetical order: bias, hard_mask, key, query, value
        k = (const float*)d_in[big[0]];
        q = (const float*)d_in[big[1]];
        v = (const float*)d_in[big[2]];
    } else {            // dict order: query, key, value, hard_mask, bias
        q = (const float*)d_in[big[0]];
        k = (const float*)d_in[big[1]];
        v = (const float*)d_in[big[2]];
    }
    const void*  mask = d_in[mask_i];
    const float* bias = (const float*)d_in[bias_i];
    float*       out  = (float*)d_out;

    cudaFuncSetAttribute(masked_attn_kernel,
                         cudaFuncAttributeMaxDynamicSharedMemorySize, SMEM_BYTES);

    detect_mask_mode<<<1, 1>>>((const unsigned int*)mask);

    dim3 grid(B_ * H_ * (L_ / QT));   // 512 blocks
    dim3 block(256);
    masked_attn_kernel<<<grid, block, SMEM_BYTES>>>(q, k, v, mask, bias, out);
}

// round 9
// speedup vs baseline: 2.5203x; 1.1754x over previous
#include <cuda_runtime.h>
#include <cuda_fp16.h>
#include <math.h>
#include <stdint.h>

#define B_   8
#define L_   1024
#define H_   8
#define D_   32
#define C_   256
#define QT   128
#define KT   64
#define NKT  (L_ / KT)
#define SCALE 0.17677669529663687f  // 1/sqrt(32)

// dynamic smem word offsets (uint32 words)
#define QHI_W    0                     // [128*20] prologue only
#define QLO_W    2560                  // [128*20] prologue only
#define RAWK_W   0                     // overlay: RawK[64][36] f32 (2304 w)
#define RAWV_W   2560                  // overlay: RawV[64][36] f32 (2304 w)
#define KHI_W    5120                  // [64*20]
#define VTHI_W   6400                  // [32*36]
#define BIAS_W   7552                  // 2 x [128*68] f32
#define BIAS_STRIDE_W 8704
#define MADD_W   (BIAS_W + 2*BIAS_STRIDE_W)   // 24960
#define SMEM_W   (MADD_W + 64)                // 25024 words
#define SMEM_BYTES (SMEM_W * 4)               // 100096 B

__device__ int g_mask_mode;

__global__ void detect_mask_mode(const unsigned int* m)
{
    bool all_f32 = true, all_i32 = true;
    for (int i = 0; i < 2048; ++i) {
        unsigned int w = m[i];
        if (w != 0u && w != 0x3f800000u) all_f32 = false;
        if (w != 0u && w != 1u)          all_i32 = false;
    }
    g_mask_mode = all_f32 ? 0 : (all_i32 ? 1 : 2);
}

__device__ __forceinline__ bool mask_at(const void* m, int idx, int mode)
{
    if (mode == 0) return ((const float*)m)[idx] != 0.0f;
    if (mode == 1) return ((const int*)m)[idx]   != 0;
    return ((const unsigned char*)m)[idx] != 0;
}

// mma.sync m16n8k16, fp16 inputs, f32 accumulate (D = A*B + D)
__device__ __forceinline__ void mma_f16(float c[4],
                                        uint32_t a0, uint32_t a1, uint32_t a2, uint32_t a3,
                                        uint32_t b0, uint32_t b1)
{
    asm("mma.sync.aligned.m16n8k16.row.col.f32.f16.f16.f32 "
        "{%0,%1,%2,%3},{%4,%5,%6,%7},{%8,%9},{%0,%1,%2,%3};"
        : "+f"(c[0]), "+f"(c[1]), "+f"(c[2]), "+f"(c[3])
        : "r"(a0), "r"(a1), "r"(a2), "r"(a3), "r"(b0), "r"(b1));
}

// pack (x,y) f32 -> f16x2 word (low half = x, high half = y)
__device__ __forceinline__ uint32_t cvt2_f16(float x, float y)
{
    uint32_t h;
    asm("cvt.rn.f16x2.f32 %0, %1, %2;" : "=r"(h) : "f"(y), "f"(x));
    return h;
}

// split (x,y) into fp16 hi word + fp16 residual word
__device__ __forceinline__ void split2_f16(float x, float y, uint32_t& hi, uint32_t& lo)
{
    uint32_t h = cvt2_f16(x, y);
    float hx, hy;
    asm("{\n\t.reg .f16 a,b;\n\tmov.b32 {a,b}, %2;\n\t"
        "cvt.f32.f16 %0, a;\n\tcvt.f32.f16 %1, b;\n\t}"
        : "=f"(hx), "=f"(hy) : "r"(h));
    lo = cvt2_f16(x - hx, y - hy);
    hi = h;
}

__device__ __forceinline__ void cp16(uint32_t dst, const void* src)
{
    asm volatile("cp.async.cg.shared.global [%0], [%1], 16;" :: "r"(dst), "l"(src) : "memory");
}
__device__ __forceinline__ void cp_commit()
{
    asm volatile("cp.async.commit_group;" ::: "memory");
}
template<int N> __device__ __forceinline__ void cp_wait()
{
    asm volatile("cp.async.wait_group %0;" :: "n"(N) : "memory");
}

__global__ __launch_bounds__(256, 2)
void masked_attn_kernel(const float* __restrict__ q,
                        const float* __restrict__ k,
                        const float* __restrict__ v,
                        const void* __restrict__ mask,
                        const float* __restrict__ bias,
                        float* __restrict__ out)
{
    extern __shared__ uint32_t smw[];
    uint32_t* Qhi  = smw + QHI_W;
    uint32_t* Qlo  = smw + QLO_W;
    float*    RawK = (float*)(smw + RAWK_W);
    float*    RawV = (float*)(smw + RAWV_W);
    uint32_t* Khi  = smw + KHI_W;
    uint32_t* Vthi = smw + VTHI_W;
    float*    BiasS= (float*)(smw + BIAS_W);
    float*    Madd = (float*)(smw + MADD_W);
    uint32_t  smem_u32 = (uint32_t)__cvta_generic_to_shared(smw);

    int blk = blockIdx.x;
    int qt  = blk & 7;
    int h   = (blk >> 3) & 7;
    int b   = blk >> 6;
    int q0  = qt * QT;

    int mode = g_mask_mode;
    int t    = threadIdx.x;
    int w    = t >> 5;
    int lane = t & 31;
    int g    = lane >> 2;
    int tq   = lane & 3;

    const float* kbase0 = k + ((size_t)(b * L_)) * C_ + h * D_;
    const float* vbase0 = v + ((size_t)(b * L_)) * C_ + h * D_;

    // ---- issue bias(0) into buf 0 ----
    {
        const float* bb = bias + ((size_t)b * L_ + q0) * L_;
        #pragma unroll
        for (int it = 0; it < 8; ++it) {
            int idx = t + it * 256;
            int row = idx >> 4, c4 = (idx & 15) * 4;
            cp16(smem_u32 + (BIAS_W + row * 68 + c4) * 4,
                 bb + (size_t)row * L_ + c4);
        }
        cp_commit();   // group: bias0
    }

    // ---- stage Q (LDG, split fp16, STS) ----
    {
        const float* qbase = q + ((size_t)(b * L_ + q0)) * C_ + h * D_;
        #pragma unroll
        for (int it = 0; it < 8; ++it) {
            int idx = t + it * 256;
            int row = idx >> 4, p = idx & 15;
            float2 f = *(const float2*)&qbase[(size_t)row * C_ + 2 * p];
            uint32_t hi, lo;
            split2_f16(f.x * SCALE, f.y * SCALE, hi, lo);
            Qhi[row * 20 + p] = hi;
            Qlo[row * 20 + p] = lo;
        }
    }
    __syncthreads();

    // ---- load Q A-fragments ----
    uint32_t aqh[8], aql[8];
    {
        int r0 = 16 * w + g;
        #pragma unroll
        for (int kt2 = 0; kt2 < 2; ++kt2) {
            int kp = tq + 8 * kt2;
            aqh[kt2 * 4 + 0] = Qhi[r0 * 20 + kp];
            aqh[kt2 * 4 + 1] = Qhi[(r0 + 8) * 20 + kp];
            aqh[kt2 * 4 + 2] = Qhi[r0 * 20 + kp + 4];
            aqh[kt2 * 4 + 3] = Qhi[(r0 + 8) * 20 + kp + 4];
            aql[kt2 * 4 + 0] = Qlo[r0 * 20 + kp];
            aql[kt2 * 4 + 1] = Qlo[(r0 + 8) * 20 + kp];
            aql[kt2 * 4 + 2] = Qlo[r0 * 20 + kp + 4];
            aql[kt2 * 4 + 3] = Qlo[(r0 + 8) * 20 + kp + 4];
        }
    }
    __syncthreads();   // Q region free -> raw overlay

    // ---- issue raw K/V (tile 0) ----
    #pragma unroll
    for (int it = 0; it < 2; ++it) {
        int idx4 = t + it * 256;
        int key = idx4 >> 3, quad = idx4 & 7;
        cp16(smem_u32 + (RAWK_W + key * 36 + quad * 4) * 4,
             kbase0 + (size_t)key * C_ + quad * 4);
        cp16(smem_u32 + (RAWV_W + key * 36 + quad * 4) * 4,
             vbase0 + (size_t)key * C_ + quad * 4);
    }
    cp_commit();   // group: raw0
    cp_wait<0>();
    __syncthreads();

    // ---- convert raw(0) -> fp16 tiles; Madd(0) ----
    {
        #pragma unroll
        for (int it = 0; it < 2; ++it) {
            int idx4 = t + it * 256;
            int key = idx4 >> 3, quad = idx4 & 7;
            float4 f = *(const float4*)&RawK[key * 36 + quad * 4];
            int p4 = quad * 2;
            Khi[key * 20 + p4]     = cvt2_f16(f.x, f.y);
            Khi[key * 20 + p4 + 1] = cvt2_f16(f.z, f.w);
        }
        #pragma unroll
        for (int it = 0; it < 2; ++it) {
            int idx2 = t + it * 256;
            int jp = idx2 >> 4, ch2 = (idx2 & 15) * 2;
            float2 a = *(const float2*)&RawV[(2 * jp) * 36 + ch2];
            float2 c = *(const float2*)&RawV[(2 * jp + 1) * 36 + ch2];
            Vthi[ch2 * 36 + jp]       = cvt2_f16(a.x, c.x);
            Vthi[(ch2 + 1) * 36 + jp] = cvt2_f16(a.y, c.y);
        }
        if (t < KT)
            Madd[t] = mask_at(mask, b * L_ + t, mode) ? 0.f : -1e9f;
    }
    __syncthreads();

    // ---- issue raw(1) ----
    #pragma unroll
    for (int it = 0; it < 2; ++it) {
        int idx4 = t + it * 256;
        int key = idx4 >> 3, quad = idx4 & 7;
        cp16(smem_u32 + (RAWK_W + key * 36 + quad * 4) * 4,
             kbase0 + (size_t)(KT + key) * C_ + quad * 4);
        cp16(smem_u32 + (RAWV_W + key * 36 + quad * 4) * 4,
             vbase0 + (size_t)(KT + key) * C_ + quad * 4);
    }
    cp_commit();   // group: raw1

    float m0 = -INFINITY, m1 = -INFINITY, l0 = 0.f, l1 = 0.f;
    float cpv[4][4];
    #pragma unroll
    for (int nb = 0; nb < 4; ++nb)
        #pragma unroll
        for (int i = 0; i < 4; ++i) cpv[nb][i] = 0.f;

    const int row0g = q0 + 16 * w + g;
    const int row1g = row0g + 8;
    const int rloc  = 16 * w + g;

    for (int kt = 0; kt < NKT; ++kt) {
        bool pf = (kt + 1) < NKT;
        float maddpre = 0.f;

        // ---- issue bias(kt+1); prefetch mask(kt+1) ----
        if (pf) {
            int buf = (kt + 1) & 1;
            const float* bb = bias + ((size_t)b * L_ + q0) * L_ + (kt + 1) * KT;
            #pragma unroll
            for (int it = 0; it < 8; ++it) {
                int idx = t + it * 256;
                int row = idx >> 4, c4 = (idx & 15) * 4;
                cp16(smem_u32 + (BIAS_W + buf * BIAS_STRIDE_W + row * 68 + c4) * 4,
                     bb + (size_t)row * L_ + c4);
            }
            cp_commit();
            if (t < KT)
                maddpre = mask_at(mask, b * L_ + (kt + 1) * KT + t, mode) ? 0.f : -1e9f;
        }

        // ---- QK^T: C init = bias(smem) + mask ----
        const float* bs = BiasS + (kt & 1) * BIAS_STRIDE_W;
        float cqk[8][4];
        #pragma unroll
        for (int nb = 0; nb < 8; ++nb) {
            int j0 = nb * 8 + 2 * tq;
            float2 md = *(const float2*)&Madd[j0];
            float2 b0 = *(const float2*)&bs[rloc * 68 + j0];
            float2 b1 = *(const float2*)&bs[(rloc + 8) * 68 + j0];
            cqk[nb][0] = b0.x + md.x;
            cqk[nb][1] = b0.y + md.y;
            cqk[nb][2] = b1.x + md.x;
            cqk[nb][3] = b1.y + md.y;
        }
        #pragma unroll
        for (int nb = 0; nb < 8; ++nb) {
            int key = nb * 8 + g;
            #pragma unroll
            for (int kt2 = 0; kt2 < 2; ++kt2) {
                int kp = tq + 8 * kt2;
                uint32_t bh0 = Khi[key * 20 + kp], bh1 = Khi[key * 20 + kp + 4];
                const uint32_t* ah = aqh + kt2 * 4;
                const uint32_t* al = aql + kt2 * 4;
                mma_f16(cqk[nb], ah[0], ah[1], ah[2], ah[3], bh0, bh1);
                mma_f16(cqk[nb], al[0], al[1], al[2], al[3], bh0, bh1);
            }
        }

        // ---- online softmax ----
        float mt0 = -INFINITY, mt1 = -INFINITY;
        #pragma unroll
        for (int nb = 0; nb < 8; ++nb) {
            mt0 = fmaxf(mt0, fmaxf(cqk[nb][0], cqk[nb][1]));
            mt1 = fmaxf(mt1, fmaxf(cqk[nb][2], cqk[nb][3]));
        }
        mt0 = fmaxf(mt0, __shfl_xor_sync(0xffffffffu, mt0, 1));
        mt0 = fmaxf(mt0, __shfl_xor_sync(0xffffffffu, mt0, 2));
        mt1 = fmaxf(mt1, __shfl_xor_sync(0xffffffffu, mt1, 1));
        mt1 = fmaxf(mt1, __shfl_xor_sync(0xffffffffu, mt1, 2));

        float mn0 = fmaxf(m0, mt0), mn1 = fmaxf(m1, mt1);
        float f0 = __expf(m0 - mn0), f1 = __expf(m1 - mn1);
        l0 *= f0; l1 *= f1;
        #pragma unroll
        for (int nb = 0; nb < 4; ++nb) {
            cpv[nb][0] *= f0; cpv[nb][1] *= f0;
            cpv[nb][2] *= f1; cpv[nb][3] *= f1;
        }
        #pragma unroll
        for (int nb = 0; nb < 8; ++nb) {
            cqk[nb][0] = __expf(cqk[nb][0] - mn0);
            cqk[nb][1] = __expf(cqk[nb][1] - mn0);
            cqk[nb][2] = __expf(cqk[nb][2] - mn1);
            cqk[nb][3] = __expf(cqk[nb][3] - mn1);
            l0 += cqk[nb][0] + cqk[nb][1];
            l1 += cqk[nb][2] + cqk[nb][3];
        }
        m0 = mn0; m1 = mn1;

        // ---- P*V (2-term fp16: P split, V hi only) ----
        #pragma unroll
        for (int kk = 0; kk < 4; ++kk) {
            uint32_t ap[4], al[4];
            split2_f16(cqk[2 * kk][0],     cqk[2 * kk][1],     ap[0], al[0]);
            split2_f16(cqk[2 * kk][2],     cqk[2 * kk][3],     ap[1], al[1]);
            split2_f16(cqk[2 * kk + 1][0], cqk[2 * kk + 1][1], ap[2], al[2]);
            split2_f16(cqk[2 * kk + 1][2], cqk[2 * kk + 1][3], ap[3], al[3]);
            #pragma unroll
            for (int nb = 0; nb < 4; ++nb) {
                int ch = nb * 8 + g;
                int jp = 8 * kk + tq;
                uint32_t bh0 = Vthi[ch * 36 + jp], bh1 = Vthi[ch * 36 + jp + 4];
                mma_f16(cpv[nb], ap[0], ap[1], ap[2], ap[3], bh0, bh1);
                mma_f16(cpv[nb], al[0], al[1], al[2], al[3], bh0, bh1);
            }
        }

        // ---- pipeline turn: convert raw(kt+1), issue raw(kt+2) ----
        if (pf) {
            cp_wait<0>();
            __syncthreads();
            #pragma unroll
            for (int it = 0; it < 2; ++it) {
                int idx4 = t + it * 256;
                int key = idx4 >> 3, quad = idx4 & 7;
                float4 f = *(const float4*)&RawK[key * 36 + quad * 4];
                int p4 = quad * 2;
                Khi[key * 20 + p4]     = cvt2_f16(f.x, f.y);
                Khi[key * 20 + p4 + 1] = cvt2_f16(f.z, f.w);
            }
            #pragma unroll
            for (int it = 0; it < 2; ++it) {
                int idx2 = t + it * 256;
                int jp = idx2 >> 4, ch2 = (idx2 & 15) * 2;
                float2 a = *(const float2*)&RawV[(2 * jp) * 36 + ch2];
                float2 c = *(const float2*)&RawV[(2 * jp + 1) * 36 + ch2];
                Vthi[ch2 * 36 + jp]       = cvt2_f16(a.x, c.x);
                Vthi[(ch2 + 1) * 36 + jp] = cvt2_f16(a.y, c.y);
            }
            if (t < KT) Madd[t] = maddpre;
            __syncthreads();
            if (kt + 2 < NKT) {
                #pragma unroll
                for (int it = 0; it < 2; ++it) {
                    int idx4 = t + it * 256;
                    int key = idx4 >> 3, quad = idx4 & 7;
                    cp16(smem_u32 + (RAWK_W + key * 36 + quad * 4) * 4,
                         kbase0 + (size_t)((kt + 2) * KT + key) * C_ + quad * 4);
                    cp16(smem_u32 + (RAWV_W + key * 36 + quad * 4) * 4,
                         vbase0 + (size_t)((kt + 2) * KT + key) * C_ + quad * 4);
                }
                cp_commit();
            }
        }
    }

    // ---- epilogue ----
    l0 += __shfl_xor_sync(0xffffffffu, l0, 1);
    l0 += __shfl_xor_sync(0xffffffffu, l0, 2);
    l1 += __shfl_xor_sync(0xffffffffu, l1, 1);
    l1 += __shfl_xor_sync(0xffffffffu, l1, 2);
    float inv0 = 1.f / l0, inv1 = 1.f / l1;

    bool act0 = mask_at(mask, b * L_ + row0g, mode);
    bool act1 = mask_at(mask, b * L_ + row1g, mode);

    #pragma unroll
    for (int nb = 0; nb < 4; ++nb) {
        int ch = nb * 8 + 2 * tq;
        float2 o0, o1;
        if (act0) {
            o0 = make_float2(cpv[nb][0] * inv0, cpv[nb][1] * inv0);
        } else {
            o0 = *(const float2*)&v[((size_t)(b * L_ + row0g)) * C_ + h * D_ + ch];
        }
        if (act1) {
            o1 = make_float2(cpv[nb][2] * inv1, cpv[nb][3] * inv1);
        } else {
            o1 = *(const float2*)&v[((size_t)(b * L_ + row1g)) * C_ + h * D_ + ch];
        }
        *(float2*)&out[((size_t)(b * L_ + row0g)) * C_ + h * D_ + ch] = o0;
        *(float2*)&out[((size_t)(b * L_ + row1g)) * C_ + h * D_ + ch] = o1;
    }
}

extern "C" void kernel_launch(void* const* d_in, const int* in_sizes, int n_in,
                              void* d_out, int out_size)
{
    const int QKV_N  = B_ * L_ * C_;
    const int BIAS_N = B_ * L_ * L_;
    const int MASK_N = B_ * L_;

    int bias_i = -1, mask_i = -1;
    int big[3]; int nbig = 0;
    for (int i = 0; i < n_in; ++i) {
        if (in_sizes[i] == BIAS_N) bias_i = i;
        else if (in_sizes[i] == MASK_N) mask_i = i;
        else if (in_sizes[i] == QKV_N && nbig < 3) big[nbig++] = i;
    }

    const float* q; const float* k; const float* v;
    if (bias_i == 0) {  // alphabetical order: bias, hard_mask, key, query, value
        k = (const float*)d_in[big[0]];
        q = (const float*)d_in[big[1]];
        v = (const float*)d_in[big[2]];
    } else {            // dict order: query, key, value, hard_mask, bias
        q = (const float*)d_in[big[0]];
        k = (const float*)d_in[big[1]];
        v = (const float*)d_in[big[2]];
    }
    const void*  mask = d_in[mask_i];
    const float* bias = (const float*)d_in[bias_i];
    float*       out  = (float*)d_out;

    cudaFuncSetAttribute(masked_attn_kernel,
                         cudaFuncAttributeMaxDynamicSharedMemorySize, SMEM_BYTES);

    detect_mask_mode<<<1, 1>>>((const unsigned int*)mask);

    dim3 grid(B_ * H_ * (L_ / QT));   // 512 blocks
    dim3 block(256);
    masked_attn_kernel<<<grid, block, SMEM_BYTES>>>(q, k, v, mask, bias, out);
}